// round 6
// baseline (speedup 1.0000x reference)
#include <cuda_runtime.h>
#include <cstdint>

#define RELS 3
#define NMAX 50000
#define HD   256      // H = HF*AH
#define KIN  128      // in_feats

// ---------------- scratch (static device globals; no allocation) ----------------
__device__ float g_hd   [(size_t)NMAX * HD];          // 51.2 MB
__device__ float g_hw   [(size_t)RELS * NMAX * HD];   // 153.6 MB
__device__ float g_num  [(size_t)NMAX * RELS * HD];   // 153.6 MB (concat layout [N, 768])
__device__ float g_denom[(size_t)RELS * NMAX * 4];    // [r][n][head]
__device__ float g_p1   [NMAX];
__device__ float g_p2   [NMAX];
__device__ float g_qs   [(size_t)RELS * NMAX * 4];
__device__ float g_qd   [(size_t)RELS * NMAX * 4];
__device__ float g_f1   [HD];
__device__ float g_f2   [HD];

// ---------------- helpers ----------------
__device__ __forceinline__ void red_add_v4(float* p, float x, float y, float z, float w) {
    asm volatile("red.global.add.v4.f32 [%0], {%1, %2, %3, %4};"
                 :: "l"(p), "f"(x), "f"(y), "f"(z), "f"(w) : "memory");
}

// ---------------- zero-init kernels ----------------
__global__ void zero_num_kernel(size_t n4) {
    size_t i = (size_t)blockIdx.x * blockDim.x + threadIdx.x;
    if (i < n4) reinterpret_cast<float4*>(g_num)[i] = make_float4(0.f, 0.f, 0.f, 0.f);
}
__global__ void zero_den_kernel(int n) {
    int i = blockIdx.x * blockDim.x + threadIdx.x;
    if (i < n) g_denom[i] = 0.f;
}

// ---------------- fW folding: f1 = fW[0:256]+fW[512:768], f2 = fW[256:512]-fW[512:768]
__global__ void prep_f_kernel(const float* __restrict__ fW) {
    int c = threadIdx.x;
    g_f1[c] = fW[c]       + fW[512 + c];
    g_f2[c] = fW[256 + c] - fW[512 + c];
}

// ---------------- tiled fp32 GEMM: C[M,N] = A[M,K] @ B[K,N] + bias[N] ----------------
// BM=128, BN=64, BK=16, TM=8, TN=4, 256 threads. Requires N%64==0, K%16==0, 16B-aligned rows.
#define GBM 128
#define GBN 64
#define GBK 16
__global__ __launch_bounds__(256) void gemm_bias_kernel(
    const float* __restrict__ A, const float* __restrict__ B,
    const float* __restrict__ bias, float* __restrict__ C,
    int M, int N, int K)
{
    __shared__ float As[GBK][GBM + 4];
    __shared__ float Bs[GBK][GBN];

    const int tid = threadIdx.x;
    const int tx = tid & 15;          // 0..15 -> 64 cols (4 each)
    const int ty = tid >> 4;          // 0..15 -> 128 rows (8 each)
    const int block_m = blockIdx.y * GBM;
    const int block_n = blockIdx.x * GBN;

    float acc[8][4];
#pragma unroll
    for (int i = 0; i < 8; i++)
#pragma unroll
        for (int j = 0; j < 4; j++) acc[i][j] = 0.f;

    const int b_row = tid >> 4;            // 0..15
    const int b_col = (tid & 15) << 2;     // 0..60

    for (int k0 = 0; k0 < K; k0 += GBK) {
        // load A tile (128x16) -> As transposed; 512 float4, 2 per thread
#pragma unroll
        for (int f = tid; f < (GBM * GBK) / 4; f += 256) {
            int row = f >> 2;
            int kq  = (f & 3) << 2;
            int gm  = block_m + row;
            float4 av = make_float4(0.f, 0.f, 0.f, 0.f);
            if (gm < M) av = *reinterpret_cast<const float4*>(A + (size_t)gm * K + k0 + kq);
            As[kq + 0][row] = av.x;
            As[kq + 1][row] = av.y;
            As[kq + 2][row] = av.z;
            As[kq + 3][row] = av.w;
        }
        // load B tile (16x64); 256 float4, 1 per thread
        {
            float4 bv = *reinterpret_cast<const float4*>(B + (size_t)(k0 + b_row) * N + block_n + b_col);
            *reinterpret_cast<float4*>(&Bs[b_row][b_col]) = bv;
        }
        __syncthreads();

#pragma unroll
        for (int k = 0; k < GBK; k++) {
            float4 ra0 = *reinterpret_cast<const float4*>(&As[k][ty * 8]);
            float4 ra1 = *reinterpret_cast<const float4*>(&As[k][ty * 8 + 4]);
            float4 rb  = *reinterpret_cast<const float4*>(&Bs[k][tx * 4]);
            float ra[8] = {ra0.x, ra0.y, ra0.z, ra0.w, ra1.x, ra1.y, ra1.z, ra1.w};
            float rbv[4] = {rb.x, rb.y, rb.z, rb.w};
#pragma unroll
            for (int i = 0; i < 8; i++)
#pragma unroll
                for (int j = 0; j < 4; j++)
                    acc[i][j] = fmaf(ra[i], rbv[j], acc[i][j]);
        }
        __syncthreads();
    }

    // epilogue
    int n = block_n + tx * 4;
    float4 bb = *reinterpret_cast<const float4*>(bias + n);
#pragma unroll
    for (int i = 0; i < 8; i++) {
        int m = block_m + ty * 8 + i;
        if (m >= M) continue;
        float4 o;
        o.x = acc[i][0] + bb.x;
        o.y = acc[i][1] + bb.y;
        o.z = acc[i][2] + bb.z;
        o.w = acc[i][3] + bb.w;
        *reinterpret_cast<float4*>(C + (size_t)m * N + n) = o;
    }
}

// ---------------- per-node scalars: p1,p2 (from hd) and qs,qd per relation/head ----------------
__global__ void scalars_kernel(const float* __restrict__ aW, int N) {
    int warp = (blockIdx.x * blockDim.x + threadIdx.x) >> 5;
    int lane = threadIdx.x & 31;
    if (warp >= N) return;

    // p1, p2 : dot(hd[n], f1/f2), 256 wide -> 8 per lane
    const float4* hdrow = reinterpret_cast<const float4*>(g_hd + (size_t)warp * HD);
    float s1 = 0.f, s2 = 0.f;
#pragma unroll
    for (int q = 0; q < 2; q++) {
        int c4 = lane * 2 + q;                     // 0..63
        float4 v  = hdrow[c4];
        float4 f1 = reinterpret_cast<const float4*>(g_f1)[c4];
        float4 f2 = reinterpret_cast<const float4*>(g_f2)[c4];
        s1 += v.x * f1.x + v.y * f1.y + v.z * f1.z + v.w * f1.w;
        s2 += v.x * f2.x + v.y * f2.y + v.z * f2.z + v.w * f2.w;
    }
#pragma unroll
    for (int o = 16; o > 0; o >>= 1) {
        s1 += __shfl_xor_sync(0xFFFFFFFFu, s1, o);
        s2 += __shfl_xor_sync(0xFFFFFFFFu, s2, o);
    }
    if (lane == 0) { g_p1[warp] = s1; g_p2[warp] = s2; }

    // qs[n,a] = hw[n, a*64 : a*64+64] . aW[r][0:64] ; qd likewise with aW[r][64:128]
    int a   = lane >> 3;
    int sub = lane & 7;
#pragma unroll
    for (int r = 0; r < RELS; r++) {
        const float4* hwrow = reinterpret_cast<const float4*>(g_hw + ((size_t)r * N + warp) * HD);
        const float4* aw    = reinterpret_cast<const float4*>(aW + r * 128);
        float t1 = 0.f, t2 = 0.f;
#pragma unroll
        for (int q = 0; q < 2; q++) {
            int within = sub * 2 + q;              // 0..15 float4 within head slice
            float4 v  = hwrow[a * 16 + within];
            float4 w1 = aw[within];
            float4 w2 = aw[16 + within];
            t1 += v.x * w1.x + v.y * w1.y + v.z * w1.z + v.w * w1.w;
            t2 += v.x * w2.x + v.y * w2.y + v.z * w2.z + v.w * w2.w;
        }
#pragma unroll
        for (int o = 4; o > 0; o >>= 1) {
            t1 += __shfl_xor_sync(0xFFFFFFFFu, t1, o);
            t2 += __shfl_xor_sync(0xFFFFFFFFu, t2, o);
        }
        if (sub == 0) {
            g_qs[((size_t)r * N + warp) * 4 + a] = t1;
            g_qd[((size_t)r * N + warp) * 4 + a] = t2;
        }
    }
}

// ---------------- edge kernel: one warp per edge ----------------
// alpha = leaky_relu(sign*qs[src,a] + qd[dst,a] + ab); ex = exp(alpha)
// denom[dst,a] += ex ; num[dst, r*256 + a*64 + j] += ex*sign*hw[src, a*64+j]
__global__ __launch_bounds__(256) void edge_kernel(
    const int* __restrict__ src, const int* __restrict__ dst,
    int r, const float* __restrict__ fb, const float* __restrict__ abr,
    int E, int N)
{
    int warp = (blockIdx.x * blockDim.x + threadIdx.x) >> 5;
    int lane = threadIdx.x & 31;
    if (warp >= E) return;

    const int s = __ldg(src + warp);
    const int d = __ldg(dst + warp);

    float score = g_p1[s] + g_p2[d] + fb[0];
    float sgn = (score > 0.f) ? 1.f : ((score < 0.f) ? -1.f : 0.f);

    const float* qsr = g_qs + (size_t)r * N * 4;
    const float* qdr = g_qd + (size_t)r * N * 4;
    int a = lane >> 3;
    float x = sgn * qsr[s * 4 + a] + qdr[d * 4 + a] + abr[0];
    float alpha = (x > 0.f) ? x : 0.01f * x;
    float ex = expf(alpha);

    if ((lane & 7) == 0)
        atomicAdd(g_denom + ((size_t)r * N + d) * 4 + a, ex);

    float v = ex * sgn;
    const float4* hrow = reinterpret_cast<const float4*>(g_hw + ((size_t)r * N + s) * HD) + lane * 2;
    float4 h0 = hrow[0];
    float4 h1 = hrow[1];
    float* out = g_num + (size_t)d * (RELS * HD) + r * HD + lane * 8;
    red_add_v4(out,     v * h0.x, v * h0.y, v * h0.z, v * h0.w);
    red_add_v4(out + 4, v * h1.x, v * h1.y, v * h1.z, v * h1.w);
}

// ---------------- divide numerator by denom (guard empty segments) ----------------
__global__ void div_kernel(int N) {
    int i = blockIdx.x * blockDim.x + threadIdx.x;   // float4 index into g_num
    int total = N * (RELS * HD / 4);                 // N * 192
    if (i >= total) return;
    int n  = i / 192;
    int c4 = i - n * 192;
    int r  = c4 >> 6;              // 64 float4 per relation
    int a  = (c4 & 63) >> 4;       // 16 float4 per head
    float den = g_denom[((size_t)r * N + n) * 4 + a];
    float sc = (den > 0.f) ? (1.f / den) : 0.f;
    float4* p = reinterpret_cast<float4*>(g_num) + i;
    float4 v = *p;
    v.x *= sc; v.y *= sc; v.z *= sc; v.w *= sc;
    *p = v;
}

// ---------------- launch ----------------
extern "C" void kernel_launch(void* const* d_in, const int* in_sizes, int n_in,
                              void* d_out, int out_size)
{
    const float* h    = (const float*)d_in[0];
    const float* dW   = (const float*)d_in[1];
    const float* db   = (const float*)d_in[2];
    const float* fW   = (const float*)d_in[3];
    const float* fb   = (const float*)d_in[4];
    const float* wW   = (const float*)d_in[5];
    const float* wb   = (const float*)d_in[6];
    const float* aW   = (const float*)d_in[7];
    const float* ab   = (const float*)d_in[8];
    const float* linW = (const float*)d_in[9];
    const float* linb = (const float*)d_in[10];
    const int*   src  = (const int*)d_in[11];
    const int*   dst  = (const int*)d_in[12];

    const int N = in_sizes[0] / KIN;        // 50000
    const int E = in_sizes[11] / RELS;      // 300000

    float *p_hd, *p_hw, *p_num;
    cudaGetSymbolAddress((void**)&p_hd,  g_hd);
    cudaGetSymbolAddress((void**)&p_hw,  g_hw);
    cudaGetSymbolAddress((void**)&p_num, g_num);

    // zero accumulators
    {
        size_t n4 = (size_t)N * (RELS * HD) / 4;
        zero_num_kernel<<<(unsigned)((n4 + 255) / 256), 256>>>(n4);
        int nd = RELS * N * 4;
        zero_den_kernel<<<(nd + 255) / 256, 256>>>(nd);
    }

    prep_f_kernel<<<1, 256>>>(fW);

    dim3 ggrid(HD / GBN, (N + GBM - 1) / GBM);
    // hd = h @ dW + db
    gemm_bias_kernel<<<ggrid, 256>>>(h, dW, db, p_hd, N, HD, KIN);
    // hw_r = h @ wW[r] + wb[r]
    for (int r = 0; r < RELS; r++)
        gemm_bias_kernel<<<ggrid, 256>>>(h, wW + (size_t)r * KIN * HD, wb + r * HD,
                                         p_hw + (size_t)r * N * HD, N, HD, KIN);

    // per-node scalars
    scalars_kernel<<<(N + 7) / 8, 256>>>(aW, N);

    // edge aggregation per relation
    for (int r = 0; r < RELS; r++)
        edge_kernel<<<(E + 7) / 8, 256>>>(src + (size_t)r * E, dst + (size_t)r * E,
                                          r, fb, ab + r, E, N);

    // num /= denom
    {
        int total = N * (RELS * HD / 4);
        div_kernel<<<(total + 255) / 256, 256>>>(N);
    }

    // out = cat(out_r) @ linW + linb
    gemm_bias_kernel<<<ggrid, 256>>>(p_num, linW, linb, (float*)d_out, N, HD, RELS * HD);
}